// round 1
// baseline (speedup 1.0000x reference)
#include <cuda_runtime.h>
#include <math.h>

#define NN 500000
#define EE 2000000
#define DD 64
#define HIDN 256
#define TT 100000
#define MAXSLOT 100000

// ---------------- static scratch (no allocation allowed) ----------------
__device__ float g_s[NN];              // per-node relu(h . attn)
__device__ int   g_slot[NN];           // -1 = unmarked, >=0 compact slot id
__device__ float g_m[MAXSLOT];         // segment max (scores >= 0 so init 0 is exact)
__device__ float g_den[MAXSLOT];       // segment sum of exp
__device__ float g_hneigh[MAXSLOT*DD]; // weighted neighbor sums (25.6MB)
__device__ int   g_relSrc[EE];         // compacted relevant edges: src node
__device__ int   g_relSlot[EE];        // compacted relevant edges: dst slot
__device__ float g_relEx[EE];          // exp(s - m) per relevant edge
__device__ int   g_cnt[2];             // [0]=slot count, [1]=relevant edge count

// ---------------- init ----------------
__global__ void k_init() {
    int i = blockIdx.x * blockDim.x + threadIdx.x;
    float4* h4 = (float4*)g_hneigh;
    if (i < MAXSLOT * DD / 4) h4[i] = make_float4(0.f, 0.f, 0.f, 0.f);
    if (i < NN) g_slot[i] = -1;
    if (i < MAXSLOT) { g_m[i] = 0.f; g_den[i] = 0.f; }
    if (i < 2) g_cnt[i] = 0;
}

// ---------------- per-node attention score ----------------
__global__ void k_score(const float* __restrict__ h, const float* __restrict__ attn) {
    int w = (blockIdx.x * blockDim.x + threadIdx.x) >> 5;
    int lane = threadIdx.x & 31;
    if (w >= NN) return;
    const float* hr = h + (size_t)w * DD;
    float v = hr[lane] * __ldg(attn + lane) + hr[lane + 32] * __ldg(attn + lane + 32);
    #pragma unroll
    for (int o = 16; o; o >>= 1) v += __shfl_xor_sync(0xffffffffu, v, o);
    if (lane == 0) g_s[w] = fmaxf(v, 0.f);
}

// ---------------- mark targets, assign compact slots (warp-aggregated counter) ----------------
__global__ void k_mark(const int* __restrict__ targets) {
    int t = blockIdx.x * blockDim.x + threadIdx.x;
    int node = -1;
    bool claim = false;
    if (t < TT) {
        node = targets[t];
        claim = (atomicCAS(&g_slot[node], -1, -2) == -1);
    }
    unsigned mask = __ballot_sync(0xffffffffu, claim);
    if (mask) {
        int lane = threadIdx.x & 31;
        int leader = __ffs(mask) - 1;
        int base = 0;
        if (lane == leader) base = atomicAdd(&g_cnt[0], __popc(mask));
        base = __shfl_sync(0xffffffffu, base, leader);
        if (claim) {
            int rank = __popc(mask & ((1u << lane) - 1u));
            atomicExch(&g_slot[node], base + rank);
        }
    }
}

// ---------------- edge pass 1: segment max + compact relevant edges (block-aggregated counter) ----------------
__global__ void k_edge1(const int* __restrict__ src, const int* __restrict__ dst) {
    __shared__ int sWarp[8];
    __shared__ int sBase;
    int e = blockIdx.x * blockDim.x + threadIdx.x;
    int lane = threadIdx.x & 31, wid = threadIdx.x >> 5;
    int slot = -1, sn = 0;
    if (e < EE) {
        slot = g_slot[dst[e]];
        if (slot >= 0) {
            sn = src[e];
            atomicMax((int*)&g_m[slot], __float_as_int(g_s[sn]));  // scores >= 0: int cmp valid
        }
    }
    bool rel = (slot >= 0);
    unsigned mask = __ballot_sync(0xffffffffu, rel);
    if (lane == 0) sWarp[wid] = __popc(mask);
    __syncthreads();
    if (threadIdx.x == 0) {
        int tot = 0;
        #pragma unroll
        for (int w = 0; w < 8; w++) { int c = sWarp[w]; sWarp[w] = tot; tot += c; }
        sBase = tot ? atomicAdd(&g_cnt[1], tot) : 0;
    }
    __syncthreads();
    if (rel) {
        int j = sBase + sWarp[wid] + __popc(mask & ((1u << lane) - 1u));
        g_relSrc[j] = sn;
        g_relSlot[j] = slot;
    }
}

// ---------------- edge pass 2: exp + segment denom ----------------
__global__ void k_edge2() {
    int cnt = g_cnt[1];
    int stride = gridDim.x * blockDim.x;
    for (int j = blockIdx.x * blockDim.x + threadIdx.x; j < cnt; j += stride) {
        int slot = g_relSlot[j];
        float ex = expf(g_s[g_relSrc[j]] - g_m[slot]);
        g_relEx[j] = ex;
        atomicAdd(&g_den[slot], ex);
    }
}

// ---------------- edge pass 3: weighted neighbor sum (warp per edge) ----------------
__global__ void k_edge3(const float* __restrict__ h) {
    int cnt = g_cnt[1];
    int gw = (blockIdx.x * blockDim.x + threadIdx.x) >> 5;
    int lane = threadIdx.x & 31;
    int nw = (gridDim.x * blockDim.x) >> 5;
    for (int j = gw; j < cnt; j += nw) {
        int slot = g_relSlot[j];
        int sn = g_relSrc[j];
        float a = g_relEx[j] / g_den[slot];
        const float* hr = h + (size_t)sn * DD;
        atomicAdd(&g_hneigh[slot * DD + lane],      hr[lane] * a);
        atomicAdd(&g_hneigh[slot * DD + lane + 32], hr[lane + 32] * a);
    }
}

// ---------------- fused dual-MLP + relu + gather-write ----------------
// CTA: 256 threads, tile of 64 target rows. rg = tid&31 handles rows {rg, rg+32},
// cg = tid>>5 handles 8 output cols (GEMM2) / 4 hidden cols (GEMM1).
__global__ void __launch_bounds__(256) k_mlp(
    const float* __restrict__ cell,
    const float* __restrict__ Wn1, const float* __restrict__ bn1,
    const float* __restrict__ Wn2, const float* __restrict__ bn2,
    const float* __restrict__ Ws1, const float* __restrict__ bs1,
    const float* __restrict__ Ws2, const float* __restrict__ bs2,
    const int* __restrict__ targets, float* __restrict__ out)
{
    __shared__ __align__(16) float Xs[64][68];    // 17.4KB
    __shared__ __align__(16) float W1s[64][36];   // 9.2KB
    __shared__ __align__(16) float W2s[32][68];   // 8.7KB
    __shared__ __align__(16) float Hs[64][36];    // 9.2KB
    __shared__ int rowNode[64];
    __shared__ int rowSlot[64];

    int tid = threadIdx.x;
    int rg = tid & 31;
    int cg = tid >> 5;
    int base = blockIdx.x * 64;

    if (tid < 64) {
        int gr = base + tid;
        int node = (gr < TT) ? targets[gr] : -1;
        rowNode[tid] = node;
        rowSlot[tid] = (node >= 0) ? g_slot[node] : -1;
    }

    float acc[2][8];
    #pragma unroll
    for (int r = 0; r < 2; r++)
        #pragma unroll
        for (int c = 0; c < 8; c++) acc[r][c] = 0.f;

    #pragma unroll 1
    for (int b = 0; b < 2; b++) {
        __syncthreads();
        // load X tile (branch 0: cell_feat[node]; branch 1: g_hneigh[slot])
        for (int k = tid; k < 64 * 64; k += 256) {
            int r = k >> 6, c = k & 63;
            float v = 0.f;
            if (b == 0) {
                int p = rowNode[r];
                if (p >= 0) v = cell[(size_t)p * 64 + c];
            } else {
                int sl = rowSlot[r];
                if (sl >= 0) v = g_hneigh[sl * 64 + c];
            }
            Xs[r][c] = v;
        }
        const float* W1 = b ? Wn1 : Ws1;
        const float* B1 = b ? bn1 : bs1;
        const float* W2 = b ? Wn2 : Ws2;

        #pragma unroll 1
        for (int chunk = 0; chunk < 8; chunk++) {
            int k0 = chunk * 32;
            __syncthreads();  // previous chunk's GEMM2 done before overwriting W/H
            // load W1 chunk [64 x 32] and W2 chunk [32 x 64]
            for (int k = tid; k < 2048; k += 256) {
                int i = k >> 5, kk = k & 31;
                W1s[i][kk] = W1[i * HIDN + k0 + kk];
            }
            for (int k = tid; k < 2048; k += 256) {
                int kk = k >> 6, j = k & 63;
                W2s[kk][j] = W2[(k0 + kk) * 64 + j];
            }
            __syncthreads();

            // GEMM1: hidden chunk = relu(X @ W1chunk + b1chunk)
            float h0[4], h1[4];
            #pragma unroll
            for (int c = 0; c < 4; c++) {
                float bv = __ldg(&B1[k0 + cg * 4 + c]);
                h0[c] = bv; h1[c] = bv;
            }
            #pragma unroll
            for (int i = 0; i < 64; i += 4) {
                float4 x0 = *(const float4*)&Xs[rg][i];
                float4 x1 = *(const float4*)&Xs[rg + 32][i];
                float x0a[4] = {x0.x, x0.y, x0.z, x0.w};
                float x1a[4] = {x1.x, x1.y, x1.z, x1.w};
                #pragma unroll
                for (int ii = 0; ii < 4; ii++) {
                    float4 w = *(const float4*)&W1s[i + ii][cg * 4];
                    h0[0] = fmaf(x0a[ii], w.x, h0[0]);
                    h0[1] = fmaf(x0a[ii], w.y, h0[1]);
                    h0[2] = fmaf(x0a[ii], w.z, h0[2]);
                    h0[3] = fmaf(x0a[ii], w.w, h0[3]);
                    h1[0] = fmaf(x1a[ii], w.x, h1[0]);
                    h1[1] = fmaf(x1a[ii], w.y, h1[1]);
                    h1[2] = fmaf(x1a[ii], w.z, h1[2]);
                    h1[3] = fmaf(x1a[ii], w.w, h1[3]);
                }
            }
            *(float4*)&Hs[rg][cg * 4] =
                make_float4(fmaxf(h0[0],0.f), fmaxf(h0[1],0.f), fmaxf(h0[2],0.f), fmaxf(h0[3],0.f));
            *(float4*)&Hs[rg + 32][cg * 4] =
                make_float4(fmaxf(h1[0],0.f), fmaxf(h1[1],0.f), fmaxf(h1[2],0.f), fmaxf(h1[3],0.f));
            __syncthreads();

            // GEMM2: acc += Hchunk @ W2chunk
            #pragma unroll
            for (int kk = 0; kk < 32; kk += 4) {
                float4 a0 = *(const float4*)&Hs[rg][kk];
                float4 a1 = *(const float4*)&Hs[rg + 32][kk];
                float v0[4] = {a0.x, a0.y, a0.z, a0.w};
                float v1[4] = {a1.x, a1.y, a1.z, a1.w};
                #pragma unroll
                for (int ii = 0; ii < 4; ii++) {
                    float4 wA = *(const float4*)&W2s[kk + ii][cg * 8];
                    float4 wB = *(const float4*)&W2s[kk + ii][cg * 8 + 4];
                    acc[0][0] = fmaf(v0[ii], wA.x, acc[0][0]);
                    acc[0][1] = fmaf(v0[ii], wA.y, acc[0][1]);
                    acc[0][2] = fmaf(v0[ii], wA.z, acc[0][2]);
                    acc[0][3] = fmaf(v0[ii], wA.w, acc[0][3]);
                    acc[0][4] = fmaf(v0[ii], wB.x, acc[0][4]);
                    acc[0][5] = fmaf(v0[ii], wB.y, acc[0][5]);
                    acc[0][6] = fmaf(v0[ii], wB.z, acc[0][6]);
                    acc[0][7] = fmaf(v0[ii], wB.w, acc[0][7]);
                    acc[1][0] = fmaf(v1[ii], wA.x, acc[1][0]);
                    acc[1][1] = fmaf(v1[ii], wA.y, acc[1][1]);
                    acc[1][2] = fmaf(v1[ii], wA.z, acc[1][2]);
                    acc[1][3] = fmaf(v1[ii], wA.w, acc[1][3]);
                    acc[1][4] = fmaf(v1[ii], wB.x, acc[1][4]);
                    acc[1][5] = fmaf(v1[ii], wB.y, acc[1][5]);
                    acc[1][6] = fmaf(v1[ii], wB.z, acc[1][6]);
                    acc[1][7] = fmaf(v1[ii], wB.w, acc[1][7]);
                }
            }
        }
    }

    // epilogue: out = relu(accS + accN + bs2 + bn2)
    int j0 = cg * 8;
    float4 bsA = __ldg((const float4*)&bs2[j0]);
    float4 bsB = __ldg((const float4*)&bs2[j0 + 4]);
    float4 bnA = __ldg((const float4*)&bn2[j0]);
    float4 bnB = __ldg((const float4*)&bn2[j0 + 4]);
    float bb[8] = {bsA.x + bnA.x, bsA.y + bnA.y, bsA.z + bnA.z, bsA.w + bnA.w,
                   bsB.x + bnB.x, bsB.y + bnB.y, bsB.z + bnB.z, bsB.w + bnB.w};
    #pragma unroll
    for (int r = 0; r < 2; r++) {
        int gr = base + rg + r * 32;
        if (gr < TT) {
            float4 oA = make_float4(fmaxf(acc[r][0]+bb[0],0.f), fmaxf(acc[r][1]+bb[1],0.f),
                                    fmaxf(acc[r][2]+bb[2],0.f), fmaxf(acc[r][3]+bb[3],0.f));
            float4 oB = make_float4(fmaxf(acc[r][4]+bb[4],0.f), fmaxf(acc[r][5]+bb[5],0.f),
                                    fmaxf(acc[r][6]+bb[6],0.f), fmaxf(acc[r][7]+bb[7],0.f));
            *(float4*)&out[(size_t)gr * 64 + j0]     = oA;
            *(float4*)&out[(size_t)gr * 64 + j0 + 4] = oB;
        }
    }
}

// ---------------- launch ----------------
extern "C" void kernel_launch(void* const* d_in, const int* in_sizes, int n_in,
                              void* d_out, int out_size) {
    const float* h        = (const float*)d_in[0];
    const float* cell     = (const float*)d_in[1];
    const float* attn     = (const float*)d_in[2];
    const float* Wn1      = (const float*)d_in[3];
    const float* bn1      = (const float*)d_in[4];
    const float* Wn2      = (const float*)d_in[5];
    const float* bn2      = (const float*)d_in[6];
    const float* Ws1      = (const float*)d_in[7];
    const float* bs1      = (const float*)d_in[8];
    const float* Ws2      = (const float*)d_in[9];
    const float* bs2      = (const float*)d_in[10];
    const int*   src      = (const int*)d_in[11];
    const int*   dst      = (const int*)d_in[12];
    const int*   targets  = (const int*)d_in[13];
    float* out = (float*)d_out;

    k_init<<<(MAXSLOT * DD / 4 + 255) / 256, 256>>>();
    k_score<<<(NN * 32 + 255) / 256, 256>>>(h, attn);
    k_mark<<<(TT + 255) / 256, 256>>>(targets);
    k_edge1<<<(EE + 255) / 256, 256>>>(src, dst);
    k_edge2<<<2048, 256>>>();
    k_edge3<<<4096, 256>>>(h);
    k_mlp<<<(TT + 63) / 64, 256>>>(cell, Wn1, bn1, Wn2, bn2, Ws1, bs1, Ws2, bs2,
                                   targets, out);
}

// round 3
// speedup vs baseline: 1.0494x; 1.0494x over previous
#include <cuda_runtime.h>
#include <cuda_bf16.h>
#include <mma.h>
#include <math.h>
#include <stdint.h>

using namespace nvcuda;

#define NN 500000
#define EE 2000000
#define DD 64
#define HIDN 256
#define TT 100000
#define MAXSLOT 100000
#define NTILE ((TT + 127) / 128)   // 782
#define GRID_MLP 148

// ================= static scratch =================
__device__ float g_s[NN];
__device__ int   g_slot[NN];
__device__ float g_m[MAXSLOT];
__device__ float g_den[MAXSLOT];
__device__ float g_hneigh[MAXSLOT * DD];
__device__ int   g_relSrc[EE];
__device__ int   g_relSlot[EE];
__device__ float g_relEx[EE];
__device__ int   g_cnt[2];
// pre-split weights (bf16 hi/lo), plain row-major, k-major layouts:
// g_W1s[b][p] : [64 k][256 n]   g_W2s[b][p] : [256 k][64 n]
__device__ __align__(16) unsigned short g_W1s[2][2][64 * 256];
__device__ __align__(16) unsigned short g_W2s[2][2][256 * 64];

// ================= init =================
__global__ void k_init() {
    int i = blockIdx.x * blockDim.x + threadIdx.x;
    float4* h4 = (float4*)g_hneigh;
    if (i < MAXSLOT * DD / 4) h4[i] = make_float4(0.f, 0.f, 0.f, 0.f);
    if (i < NN) g_slot[i] = -1;
    if (i < MAXSLOT) { g_m[i] = 0.f; g_den[i] = 0.f; }
    if (i < 2) g_cnt[i] = 0;
}

// ================= weight split prep =================
__global__ void k_wsplit(const float* __restrict__ Ws1, const float* __restrict__ Wn1,
                         const float* __restrict__ Ws2, const float* __restrict__ Wn2) {
    int gid = blockIdx.x * blockDim.x + threadIdx.x;
    if (gid >= 65536) return;
    int half = gid >> 15;          // 0 = W1, 1 = W2
    int b = (gid >> 14) & 1;
    int e = gid & 16383;
    float v;
    if (half == 0) {
        const float* W1 = b ? Wn1 : Ws1;   // [64][256]
        v = W1[e];
        __nv_bfloat16 hi = __float2bfloat16_rn(v);
        __nv_bfloat16 lo = __float2bfloat16_rn(v - __bfloat162float(hi));
        g_W1s[b][0][e] = __bfloat16_as_ushort(hi);
        g_W1s[b][1][e] = __bfloat16_as_ushort(lo);
    } else {
        const float* W2 = b ? Wn2 : Ws2;   // [256][64]
        v = W2[e];
        __nv_bfloat16 hi = __float2bfloat16_rn(v);
        __nv_bfloat16 lo = __float2bfloat16_rn(v - __bfloat162float(hi));
        g_W2s[b][0][e] = __bfloat16_as_ushort(hi);
        g_W2s[b][1][e] = __bfloat16_as_ushort(lo);
    }
}

// ================= per-node attention score =================
__global__ void k_score(const float* __restrict__ h, const float* __restrict__ attn) {
    int w = (blockIdx.x * blockDim.x + threadIdx.x) >> 5;
    int lane = threadIdx.x & 31;
    if (w >= NN) return;
    const float* hr = h + (size_t)w * DD;
    float v = hr[lane] * __ldg(attn + lane) + hr[lane + 32] * __ldg(attn + lane + 32);
    #pragma unroll
    for (int o = 16; o; o >>= 1) v += __shfl_xor_sync(0xffffffffu, v, o);
    if (lane == 0) g_s[w] = fmaxf(v, 0.f);
}

// ================= mark targets / compact slots =================
__global__ void k_mark(const int* __restrict__ targets) {
    int t = blockIdx.x * blockDim.x + threadIdx.x;
    int node = -1;
    bool claim = false;
    if (t < TT) {
        node = targets[t];
        claim = (atomicCAS(&g_slot[node], -1, -2) == -1);
    }
    unsigned mask = __ballot_sync(0xffffffffu, claim);
    if (mask) {
        int lane = threadIdx.x & 31;
        int leader = __ffs(mask) - 1;
        int base = 0;
        if (lane == leader) base = atomicAdd(&g_cnt[0], __popc(mask));
        base = __shfl_sync(0xffffffffu, base, leader);
        if (claim) {
            int rank = __popc(mask & ((1u << lane) - 1u));
            atomicExch(&g_slot[node], base + rank);
        }
    }
}

// ================= edge pass 1 =================
__global__ void k_edge1(const int* __restrict__ src, const int* __restrict__ dst) {
    __shared__ int sWarp[8];
    __shared__ int sBase;
    int e = blockIdx.x * blockDim.x + threadIdx.x;
    int lane = threadIdx.x & 31, wid = threadIdx.x >> 5;
    int slot = -1, sn = 0;
    if (e < EE) {
        slot = g_slot[dst[e]];
        if (slot >= 0) {
            sn = src[e];
            atomicMax((int*)&g_m[slot], __float_as_int(g_s[sn]));
        }
    }
    bool rel = (slot >= 0);
    unsigned mask = __ballot_sync(0xffffffffu, rel);
    if (lane == 0) sWarp[wid] = __popc(mask);
    __syncthreads();
    if (threadIdx.x == 0) {
        int tot = 0;
        #pragma unroll
        for (int w = 0; w < 8; w++) { int c = sWarp[w]; sWarp[w] = tot; tot += c; }
        sBase = tot ? atomicAdd(&g_cnt[1], tot) : 0;
    }
    __syncthreads();
    if (rel) {
        int j = sBase + sWarp[wid] + __popc(mask & ((1u << lane) - 1u));
        g_relSrc[j] = sn;
        g_relSlot[j] = slot;
    }
}

// ================= edge pass 2 =================
__global__ void k_edge2() {
    int cnt = g_cnt[1];
    int stride = gridDim.x * blockDim.x;
    for (int j = blockIdx.x * blockDim.x + threadIdx.x; j < cnt; j += stride) {
        int slot = g_relSlot[j];
        float ex = expf(g_s[g_relSrc[j]] - g_m[slot]);
        g_relEx[j] = ex;
        atomicAdd(&g_den[slot], ex);
    }
}

// ================= edge pass 3 =================
__global__ void k_edge3(const float* __restrict__ h) {
    int cnt = g_cnt[1];
    int gw = (blockIdx.x * blockDim.x + threadIdx.x) >> 5;
    int lane = threadIdx.x & 31;
    int nw = (gridDim.x * blockDim.x) >> 5;
    for (int j = gw; j < cnt; j += nw) {
        int slot = g_relSlot[j];
        int sn = g_relSrc[j];
        float a = g_relEx[j] / g_den[slot];
        const float* hr = h + (size_t)sn * DD;
        atomicAdd(&g_hneigh[slot * DD + lane],      hr[lane] * a);
        atomicAdd(&g_hneigh[slot * DD + lane + 32], hr[lane + 32] * a);
    }
}

// ================= WMMA fused dual-MLP =================
// SMEM byte offsets (all multiples of 32B; bf16 row stride 72 elems = 144B)
#define OFF_X   0u               // 4 arrays [128][72] bf16: (b*2+p)*18432
#define OFF_H   73728u           // 2 arrays [128][72] bf16: p*18432
#define OFF_W1  110592u          // 2 arrays [64][72] bf16: p*9216
#define OFF_W2  129024u          // 2 arrays [64][72] bf16: p*9216
#define OFF_STG 147456u          // 8 warps x [16][72] f32: wid*4608
#define OFF_SB1 184320u          // [2][256] f32
#define OFF_SB2 186368u          // [64] f32
#define SMEM_TOTAL 186624u

typedef wmma::fragment<wmma::matrix_a, 16, 16, 16, __nv_bfloat16, wmma::row_major> FragA;
typedef wmma::fragment<wmma::matrix_b, 16, 16, 16, __nv_bfloat16, wmma::row_major> FragB;
typedef wmma::fragment<wmma::accumulator, 16, 16, 16, float> FragC;

__device__ __forceinline__ uint32_t pack_split(float x0, float x1, uint32_t& lo_out) {
    __nv_bfloat16 h0 = __float2bfloat16_rn(x0);
    __nv_bfloat16 h1 = __float2bfloat16_rn(x1);
    __nv_bfloat16 l0 = __float2bfloat16_rn(x0 - __bfloat162float(h0));
    __nv_bfloat16 l1 = __float2bfloat16_rn(x1 - __bfloat162float(h1));
    lo_out = ((uint32_t)__bfloat16_as_ushort(l1) << 16) | __bfloat16_as_ushort(l0);
    return ((uint32_t)__bfloat16_as_ushort(h1) << 16) | __bfloat16_as_ushort(h0);
}

__global__ void __launch_bounds__(256, 1) k_mlp_wmma(
    const float* __restrict__ cell,
    const float* __restrict__ bn1, const float* __restrict__ bn2,
    const float* __restrict__ bs1, const float* __restrict__ bs2,
    const int* __restrict__ targets, float* __restrict__ out)
{
    extern __shared__ __align__(128) unsigned char sm[];
    int tid = threadIdx.x;
    int wid = tid >> 5, lane = tid & 31;

    float* sb1  = (float*)(sm + OFF_SB1);   // [2][256]
    float* sb2c = (float*)(sm + OFF_SB2);   // [64]
    sb1[tid]       = __ldg(bs1 + tid);
    sb1[256 + tid] = __ldg(bn1 + tid);
    if (tid < 64) sb2c[tid] = __ldg(bs2 + tid) + __ldg(bn2 + tid);

    float* stg = (float*)(sm + OFF_STG) + wid * 16 * 72;   // warp-private [16][72]

    #pragma unroll 1
    for (int t = blockIdx.x; t < NTILE; t += GRID_MLP) {
        // ---- load X tiles for both branches, split hi/lo ----
        __syncthreads();   // prior tile's GEMM1 done with Xs
        #pragma unroll 1
        for (int r = wid; r < 128; r += 8) {
            int gr = t * 128 + r;
            float2 v0 = make_float2(0.f, 0.f), v1 = v0;
            if (gr < TT) {
                int node = __ldg(targets + gr);
                v0 = *(const float2*)(cell + (size_t)node * 64 + lane * 2);
                int sl = g_slot[node];
                v1 = *(const float2*)(g_hneigh + (size_t)sl * 64 + lane * 2);
            }
            uint32_t off = (uint32_t)(r * 72 + lane * 2) * 2;
            uint32_t lo, hi;
            hi = pack_split(v0.x, v0.y, lo);
            *(uint32_t*)(sm + OFF_X + 0 * 18432 + off) = hi;
            *(uint32_t*)(sm + OFF_X + 1 * 18432 + off) = lo;
            hi = pack_split(v1.x, v1.y, lo);
            *(uint32_t*)(sm + OFF_X + 2 * 18432 + off) = hi;
            *(uint32_t*)(sm + OFF_X + 3 * 18432 + off) = lo;
        }
        __syncthreads();

        FragC outf[4];
        #pragma unroll
        for (int n = 0; n < 4; n++) wmma::fill_fragment(outf[n], 0.f);

        #pragma unroll 1
        for (int bc = 0; bc < 8; bc++) {
            int b = bc >> 2, c = bc & 3;
            // ---- copy weight chunks from pre-split global ----
            __syncthreads();   // prior chunk's GEMM2 done with W2c
            #pragma unroll 1
            for (int i = tid; i < 2048; i += 256) {
                int arr = i >> 9, j = i & 511;
                int row = j >> 3, q = j & 7;
                float4 v;
                unsigned char* dstp;
                if (arr < 2) {
                    v = ((const float4*)(g_W1s[b][arr] + row * 256 + c * 64))[q];
                    dstp = sm + OFF_W1 + arr * 9216 + row * 144 + q * 16;
                } else {
                    v = ((const float4*)(g_W2s[b][arr - 2] + (c * 64 + row) * 64))[q];
                    dstp = sm + OFF_W2 + (arr - 2) * 9216 + row * 144 + q * 16;
                }
                *(float4*)dstp = v;
            }
            __syncthreads();

            // ---- GEMM1: H_chunk[128x64] = X[128x64] @ W1[:, c*64:+64] ----
            const __nv_bfloat16* XH = (const __nv_bfloat16*)(sm + OFF_X + (b * 2 + 0) * 18432) + wid * 16 * 72;
            const __nv_bfloat16* XL = (const __nv_bfloat16*)(sm + OFF_X + (b * 2 + 1) * 18432) + wid * 16 * 72;
            const __nv_bfloat16* W1H = (const __nv_bfloat16*)(sm + OFF_W1);
            const __nv_bfloat16* W1L = (const __nv_bfloat16*)(sm + OFF_W1 + 9216);
            FragA Ah[4], Al[4];
            #pragma unroll
            for (int k = 0; k < 4; k++) {
                wmma::load_matrix_sync(Ah[k], XH + k * 16, 72);
                wmma::load_matrix_sync(Al[k], XL + k * 16, 72);
            }
            FragC acc[4];
            #pragma unroll
            for (int n = 0; n < 4; n++) wmma::fill_fragment(acc[n], 0.f);
            #pragma unroll
            for (int n = 0; n < 4; n++) {
                #pragma unroll
                for (int k = 0; k < 4; k++) {
                    FragB Bh, Bl;
                    wmma::load_matrix_sync(Bh, W1H + k * 16 * 72 + n * 16, 72);
                    wmma::load_matrix_sync(Bl, W1L + k * 16 * 72 + n * 16, 72);
                    wmma::mma_sync(acc[n], Ah[k], Bh, acc[n]);
                    wmma::mma_sync(acc[n], Ah[k], Bl, acc[n]);
                    wmma::mma_sync(acc[n], Al[k], Bh, acc[n]);
                }
            }

            // ---- epilogue: bias + relu + re-split into Hs (warp-private rows) ----
            #pragma unroll
            for (int n = 0; n < 4; n++)
                wmma::store_matrix_sync(stg + n * 16, acc[n], 72, wmma::mem_row_major);
            __syncwarp();
            {
                const float* bp = sb1 + b * 256 + c * 64;
                #pragma unroll
                for (int i = lane; i < 16 * 32; i += 32) {
                    int row = i >> 5, col = (i & 31) * 2;
                    float x0 = fmaxf(stg[row * 72 + col]     + bp[col],     0.f);
                    float x1 = fmaxf(stg[row * 72 + col + 1] + bp[col + 1], 0.f);
                    uint32_t lo, hi = pack_split(x0, x1, lo);
                    uint32_t off = (uint32_t)((wid * 16 + row) * 72 + col) * 2;
                    *(uint32_t*)(sm + OFF_H + off) = hi;
                    *(uint32_t*)(sm + OFF_H + 18432 + off) = lo;
                }
            }
            __syncwarp();

            // ---- GEMM2: out += H_chunk[128x64] @ W2[c*64:+64, :] ----
            const __nv_bfloat16* HH = (const __nv_bfloat16*)(sm + OFF_H) + wid * 16 * 72;
            const __nv_bfloat16* HL = (const __nv_bfloat16*)(sm + OFF_H + 18432) + wid * 16 * 72;
            const __nv_bfloat16* W2H = (const __nv_bfloat16*)(sm + OFF_W2);
            const __nv_bfloat16* W2L = (const __nv_bfloat16*)(sm + OFF_W2 + 9216);
            #pragma unroll
            for (int k = 0; k < 4; k++) {
                wmma::load_matrix_sync(Ah[k], HH + k * 16, 72);
                wmma::load_matrix_sync(Al[k], HL + k * 16, 72);
            }
            #pragma unroll
            for (int n = 0; n < 4; n++) {
                #pragma unroll
                for (int k = 0; k < 4; k++) {
                    FragB Bh, Bl;
                    wmma::load_matrix_sync(Bh, W2H + k * 16 * 72 + n * 16, 72);
                    wmma::load_matrix_sync(Bl, W2L + k * 16 * 72 + n * 16, 72);
                    wmma::mma_sync(outf[n], Ah[k], Bh, outf[n]);
                    wmma::mma_sync(outf[n], Ah[k], Bl, outf[n]);
                    wmma::mma_sync(outf[n], Al[k], Bh, outf[n]);
                }
            }
        }

        // ---- final epilogue: out = relu(acc + bs2 + bn2) ----
        #pragma unroll
        for (int n = 0; n < 4; n++)
            wmma::store_matrix_sync(stg + n * 16, outf[n], 72, wmma::mem_row_major);
        __syncwarp();
        #pragma unroll
        for (int i = lane; i < 16 * 16; i += 32) {
            int row = i >> 4, q = i & 15;
            int gr = t * 128 + wid * 16 + row;
            if (gr < TT) {
                int col = q * 4;
                float4 v = *(const float4*)(stg + row * 72 + col);
                float4 bb = *(const float4*)(sb2c + col);
                float4 ov = make_float4(fmaxf(v.x + bb.x, 0.f), fmaxf(v.y + bb.y, 0.f),
                                        fmaxf(v.z + bb.z, 0.f), fmaxf(v.w + bb.w, 0.f));
                *(float4*)(out + (size_t)gr * 64 + col) = ov;
            }
        }
        __syncwarp();   // stg safe for next tile (warp-private)
    }
}

// ================= launch =================
extern "C" void kernel_launch(void* const* d_in, const int* in_sizes, int n_in,
                              void* d_out, int out_size) {
    const float* h       = (const float*)d_in[0];
    const float* cell    = (const float*)d_in[1];
    const float* attn    = (const float*)d_in[2];
    const float* Wn1     = (const float*)d_in[3];
    const float* bn1     = (const float*)d_in[4];
    const float* Wn2     = (const float*)d_in[5];
    const float* bn2     = (const float*)d_in[6];
    const float* Ws1     = (const float*)d_in[7];
    const float* bs1     = (const float*)d_in[8];
    const float* Ws2     = (const float*)d_in[9];
    const float* bs2     = (const float*)d_in[10];
    const int*   src     = (const int*)d_in[11];
    const int*   dst     = (const int*)d_in[12];
    const int*   targets = (const int*)d_in[13];
    float* out = (float*)d_out;

    cudaFuncSetAttribute(k_mlp_wmma, cudaFuncAttributeMaxDynamicSharedMemorySize, SMEM_TOTAL);

    k_init<<<(MAXSLOT * DD / 4 + 255) / 256, 256>>>();
    k_wsplit<<<256, 256>>>(Ws1, Wn1, Ws2, Wn2);
    k_score<<<(NN * 32 + 255) / 256, 256>>>(h, attn);
    k_mark<<<(TT + 255) / 256, 256>>>(targets);
    k_edge1<<<(EE + 255) / 256, 256>>>(src, dst);
    k_edge2<<<2048, 256>>>();
    k_edge3<<<4096, 256>>>(h);
    k_mlp_wmma<<<GRID_MLP, 256, SMEM_TOTAL>>>(cell, bn1, bn2, bs1, bs2, targets, out);
}

// round 4
// speedup vs baseline: 1.2125x; 1.1555x over previous
#include <cuda_runtime.h>
#include <cuda_bf16.h>
#include <math.h>
#include <stdint.h>

#define NN 500000
#define EE 2000000
#define DD 64
#define HIDN 256
#define TT 100000
#define MAXSLOT 100000
#define NTILE ((TT + 127) / 128)   // 782
#define GRID_MLP 148

// ================= static scratch =================
__device__ float g_s[NN];
__device__ int   g_slot[NN];
__device__ float g_m[MAXSLOT];
__device__ float g_den[MAXSLOT];
__device__ float g_hneigh[MAXSLOT * DD];
__device__ int   g_relSrc[EE];
__device__ int   g_relSlot[EE];
__device__ float g_relEx[EE];
__device__ int   g_cnt[2];
// pre-split weights (bf16 hi/lo): g_W1s[b][p]: [64 k][256 n], g_W2s[b][p]: [256 k][64 n]
__device__ __align__(16) unsigned short g_W1s[2][2][64 * 256];
__device__ __align__(16) unsigned short g_W2s[2][2][256 * 64];
__device__ float g_part[(size_t)NTILE * 128 * 64];   // branch-0 partials (25.6MB)

// ================= PTX helpers =================
__device__ __forceinline__ uint32_t smem_u32(const void* p) {
    uint32_t a;
    asm("{ .reg .u64 t; cvta.to.shared.u64 t, %1; cvt.u32.u64 %0, t; }" : "=r"(a) : "l"(p));
    return a;
}
__device__ __forceinline__ void ldsm_x4(uint32_t* r, uint32_t addr) {
    asm volatile("ldmatrix.sync.aligned.m8n8.x4.shared.b16 {%0,%1,%2,%3}, [%4];"
        : "=r"(r[0]), "=r"(r[1]), "=r"(r[2]), "=r"(r[3]) : "r"(addr));
}
__device__ __forceinline__ void ldsm_x2t(uint32_t* r, uint32_t addr) {
    asm volatile("ldmatrix.sync.aligned.m8n8.x2.trans.shared.b16 {%0,%1}, [%2];"
        : "=r"(r[0]), "=r"(r[1]) : "r"(addr));
}
__device__ __forceinline__ void mma16816(float* c, const uint32_t* a, const uint32_t* b) {
    asm volatile("mma.sync.aligned.m16n8k16.row.col.f32.bf16.bf16.f32 "
        "{%0,%1,%2,%3}, {%4,%5,%6,%7}, {%8,%9}, {%0,%1,%2,%3};"
        : "+f"(c[0]), "+f"(c[1]), "+f"(c[2]), "+f"(c[3])
        : "r"(a[0]), "r"(a[1]), "r"(a[2]), "r"(a[3]), "r"(b[0]), "r"(b[1]));
}
__device__ __forceinline__ uint32_t pack_split(float x0, float x1, uint32_t& lo_out) {
    __nv_bfloat16 h0 = __float2bfloat16_rn(x0);
    __nv_bfloat16 h1 = __float2bfloat16_rn(x1);
    __nv_bfloat16 l0 = __float2bfloat16_rn(x0 - __bfloat162float(h0));
    __nv_bfloat16 l1 = __float2bfloat16_rn(x1 - __bfloat162float(h1));
    lo_out = ((uint32_t)__bfloat16_as_ushort(l1) << 16) | __bfloat16_as_ushort(l0);
    return ((uint32_t)__bfloat16_as_ushort(h1) << 16) | __bfloat16_as_ushort(h0);
}

// ================= init =================
__global__ void k_init() {
    int i = blockIdx.x * blockDim.x + threadIdx.x;
    float4* h4 = (float4*)g_hneigh;
    if (i < MAXSLOT * DD / 4) h4[i] = make_float4(0.f, 0.f, 0.f, 0.f);
    if (i < NN) g_slot[i] = -1;
    if (i < MAXSLOT) { g_m[i] = 0.f; g_den[i] = 0.f; }
    if (i < 2) g_cnt[i] = 0;
}

// ================= weight split prep =================
__global__ void k_wsplit(const float* __restrict__ Ws1, const float* __restrict__ Wn1,
                         const float* __restrict__ Ws2, const float* __restrict__ Wn2) {
    int gid = blockIdx.x * blockDim.x + threadIdx.x;
    if (gid >= 65536) return;
    int half = gid >> 15;
    int b = (gid >> 14) & 1;
    int e = gid & 16383;
    if (half == 0) {
        const float* W1 = b ? Wn1 : Ws1;   // [64][256]
        float v = W1[e];
        __nv_bfloat16 hi = __float2bfloat16_rn(v);
        __nv_bfloat16 lo = __float2bfloat16_rn(v - __bfloat162float(hi));
        g_W1s[b][0][e] = __bfloat16_as_ushort(hi);
        g_W1s[b][1][e] = __bfloat16_as_ushort(lo);
    } else {
        const float* W2 = b ? Wn2 : Ws2;   // [256][64]
        float v = W2[e];
        __nv_bfloat16 hi = __float2bfloat16_rn(v);
        __nv_bfloat16 lo = __float2bfloat16_rn(v - __bfloat162float(hi));
        g_W2s[b][0][e] = __bfloat16_as_ushort(hi);
        g_W2s[b][1][e] = __bfloat16_as_ushort(lo);
    }
}

// ================= per-node attention score =================
__global__ void k_score(const float* __restrict__ h, const float* __restrict__ attn) {
    int w = (blockIdx.x * blockDim.x + threadIdx.x) >> 5;
    int lane = threadIdx.x & 31;
    if (w >= NN) return;
    const float* hr = h + (size_t)w * DD;
    float v = hr[lane] * __ldg(attn + lane) + hr[lane + 32] * __ldg(attn + lane + 32);
    #pragma unroll
    for (int o = 16; o; o >>= 1) v += __shfl_xor_sync(0xffffffffu, v, o);
    if (lane == 0) g_s[w] = fmaxf(v, 0.f);
}

// ================= mark targets / compact slots =================
__global__ void k_mark(const int* __restrict__ targets) {
    int t = blockIdx.x * blockDim.x + threadIdx.x;
    int node = -1;
    bool claim = false;
    if (t < TT) {
        node = targets[t];
        claim = (atomicCAS(&g_slot[node], -1, -2) == -1);
    }
    unsigned mask = __ballot_sync(0xffffffffu, claim);
    if (mask) {
        int lane = threadIdx.x & 31;
        int leader = __ffs(mask) - 1;
        int base = 0;
        if (lane == leader) base = atomicAdd(&g_cnt[0], __popc(mask));
        base = __shfl_sync(0xffffffffu, base, leader);
        if (claim) {
            int rank = __popc(mask & ((1u << lane) - 1u));
            atomicExch(&g_slot[node], base + rank);
        }
    }
}

// ================= edge pass 1 =================
__global__ void k_edge1(const int* __restrict__ src, const int* __restrict__ dst) {
    __shared__ int sWarp[8];
    __shared__ int sBase;
    int e = blockIdx.x * blockDim.x + threadIdx.x;
    int lane = threadIdx.x & 31, wid = threadIdx.x >> 5;
    int slot = -1, sn = 0;
    if (e < EE) {
        slot = g_slot[dst[e]];
        if (slot >= 0) {
            sn = src[e];
            atomicMax((int*)&g_m[slot], __float_as_int(g_s[sn]));
        }
    }
    bool rel = (slot >= 0);
    unsigned mask = __ballot_sync(0xffffffffu, rel);
    if (lane == 0) sWarp[wid] = __popc(mask);
    __syncthreads();
    if (threadIdx.x == 0) {
        int tot = 0;
        #pragma unroll
        for (int w = 0; w < 8; w++) { int c = sWarp[w]; sWarp[w] = tot; tot += c; }
        sBase = tot ? atomicAdd(&g_cnt[1], tot) : 0;
    }
    __syncthreads();
    if (rel) {
        int j = sBase + sWarp[wid] + __popc(mask & ((1u << lane) - 1u));
        g_relSrc[j] = sn;
        g_relSlot[j] = slot;
    }
}

// ================= edge pass 2 =================
__global__ void k_edge2() {
    int cnt = g_cnt[1];
    int stride = gridDim.x * blockDim.x;
    for (int j = blockIdx.x * blockDim.x + threadIdx.x; j < cnt; j += stride) {
        int slot = g_relSlot[j];
        float ex = expf(g_s[g_relSrc[j]] - g_m[slot]);
        g_relEx[j] = ex;
        atomicAdd(&g_den[slot], ex);
    }
}

// ================= edge pass 3 (unnormalized; normalize at MLP load) =================
__global__ void k_edge3(const float* __restrict__ h) {
    int cnt = g_cnt[1];
    int gw = (blockIdx.x * blockDim.x + threadIdx.x) >> 5;
    int lane = threadIdx.x & 31;
    int nw = (gridDim.x * blockDim.x) >> 5;
    for (int j = gw; j < cnt; j += nw) {
        int slot = g_relSlot[j];
        int sn = g_relSrc[j];
        float a = g_relEx[j];
        const float* hr = h + (size_t)sn * DD;
        atomicAdd(&g_hneigh[slot * DD + lane],      hr[lane] * a);
        atomicAdd(&g_hneigh[slot * DD + lane + 32], hr[lane + 32] * a);
    }
}

// ================= MMA fused dual-MLP (sync-free tile loop) =================
// SMEM layout (bytes):
#define OFF_W1H 0u          // [64][264] bf16, stride 528B
#define OFF_W1L 33792u
#define OFF_W2H 67584u      // [256][72] bf16, stride 144B
#define OFF_W2L 104448u
#define OFF_XH  141312u     // [128][72] bf16
#define OFF_XL  159744u
#define OFF_HH  178176u     // [128][72] bf16 (per-chunk 64 cols used)
#define OFF_HL  196608u
#define OFF_SB1 215040u     // [2][256] f32
#define OFF_SB2 217088u     // [64] f32
#define SMEM_TOTAL 217344u

__global__ void __launch_bounds__(256, 1) k_mlp2(
    const float* __restrict__ cell,
    const float* __restrict__ bn1, const float* __restrict__ bn2,
    const float* __restrict__ bs1, const float* __restrict__ bs2,
    const int* __restrict__ targets, float* __restrict__ out)
{
    extern __shared__ __align__(128) unsigned char sm[];
    uint32_t sb = smem_u32(sm);
    int tid = threadIdx.x;
    int wid = tid >> 5, lane = tid & 31;

    float* sb1  = (float*)(sm + OFF_SB1);
    float* sb2c = (float*)(sm + OFF_SB2);
    sb1[tid]       = __ldg(bs1 + tid);
    sb1[256 + tid] = __ldg(bn1 + tid);
    if (tid < 64) sb2c[tid] = __ldg(bs2 + tid) + __ldg(bn2 + tid);

    int l15 = lane & 15;

    #pragma unroll 1
    for (int b = 0; b < 2; b++) {
        __syncthreads();   // all warps done with previous branch's weights
        // ---- load branch weights (repad into SMEM) ----
        #pragma unroll 1
        for (int i = tid; i < 2048; i += 256) {
            int row = i >> 5, q = i & 31;
            *(float4*)(sm + OFF_W1H + row * 528 + q * 16) =
                ((const float4*)(g_W1s[b][0] + row * 256))[q];
            *(float4*)(sm + OFF_W1L + row * 528 + q * 16) =
                ((const float4*)(g_W1s[b][1] + row * 256))[q];
        }
        #pragma unroll 1
        for (int i = tid; i < 2048; i += 256) {
            int row = i >> 3, q = i & 7;
            *(float4*)(sm + OFF_W2H + row * 144 + q * 16) =
                ((const float4*)(g_W2s[b][0] + row * 64))[q];
            *(float4*)(sm + OFF_W2L + row * 144 + q * 16) =
                ((const float4*)(g_W2s[b][1] + row * 64))[q];
        }
        __syncthreads();

        #pragma unroll 1
        for (int t = blockIdx.x; t < NTILE; t += GRID_MLP) {
            // ---- X gather + split (warp-private rows: wid*16 .. +15) ----
            {
                int xrow = l15, half = lane >> 4;
                int gr = t * 128 + wid * 16 + xrow;
                float scale = 1.f;
                const float4* srcr = (const float4*)cell;  // dummy init
                bool valid = (gr < TT);
                if (valid) {
                    int node = __ldg(targets + gr);
                    if (b == 0) {
                        srcr = (const float4*)(cell + (size_t)node * 64);
                    } else {
                        int sl = g_slot[node];
                        srcr = (const float4*)(g_hneigh + (size_t)sl * 64);
                        float dn = g_den[sl];
                        scale = (dn > 0.f) ? (1.f / dn) : 0.f;
                    }
                }
                uint32_t rowoff = (uint32_t)(wid * 16 + xrow) * 144 + (uint32_t)half * 64;
                #pragma unroll
                for (int q = 0; q < 8; q++) {
                    float4 v = valid ? srcr[half * 8 + q] : make_float4(0.f, 0.f, 0.f, 0.f);
                    v.x *= scale; v.y *= scale; v.z *= scale; v.w *= scale;
                    uint32_t lo0, hi0 = pack_split(v.x, v.y, lo0);
                    uint32_t lo1, hi1 = pack_split(v.z, v.w, lo1);
                    uint32_t o = rowoff + q * 8;
                    *(uint32_t*)(sm + OFF_XH + o)     = hi0;
                    *(uint32_t*)(sm + OFF_XL + o)     = lo0;
                    *(uint32_t*)(sm + OFF_XH + o + 4) = hi1;
                    *(uint32_t*)(sm + OFF_XL + o + 4) = lo1;
                }
            }
            __syncwarp();

            // ---- X A-fragments (held across chunks) ----
            uint32_t XAh[4][4], XAl[4][4];
            {
                uint32_t base = sb + (uint32_t)(wid * 16 + l15) * 144 + (uint32_t)(lane >> 4) * 16;
                #pragma unroll
                for (int k = 0; k < 4; k++) {
                    ldsm_x4(XAh[k], base + OFF_XH + k * 32);
                    ldsm_x4(XAl[k], base + OFF_XL + k * 32);
                }
            }

            float outAcc[8][4];
            #pragma unroll
            for (int n = 0; n < 8; n++)
                #pragma unroll
                for (int q = 0; q < 4; q++) outAcc[n][q] = 0.f;

            int rr = lane >> 2, cc = (lane & 3) * 2;

            #pragma unroll 1
            for (int c = 0; c < 4; c++) {
                // ---- GEMM1: acc = X @ W1[:, c*64 : +64] (3-product split) ----
                #pragma unroll
                for (int n = 0; n < 8; n++) {
                    float acc[4] = {0.f, 0.f, 0.f, 0.f};
                    uint32_t bcol = (uint32_t)(c * 64 + n * 8) * 2;
                    #pragma unroll
                    for (int k = 0; k < 4; k++) {
                        uint32_t Bh[2], Bl[2];
                        uint32_t ba = sb + (uint32_t)(k * 16 + l15) * 528 + bcol;
                        ldsm_x2t(Bh, ba + OFF_W1H);
                        ldsm_x2t(Bl, ba + OFF_W1L);
                        mma16816(acc, XAh[k], Bh);
                        mma16816(acc, XAh[k], Bl);
                        mma16816(acc, XAl[k], Bh);
                    }
                    // epilogue: bias + relu + split -> H (warp-private rows)
                    int hc = c * 64 + n * 8 + cc;
                    float bv0 = sb1[b * 256 + hc], bv1 = sb1[b * 256 + hc + 1];
                    uint32_t lo, hi;
                    uint32_t off = (uint32_t)(wid * 16 + rr) * 144 + (uint32_t)(n * 8 + cc) * 2;
                    hi = pack_split(fmaxf(acc[0] + bv0, 0.f), fmaxf(acc[1] + bv1, 0.f), lo);
                    *(uint32_t*)(sm + OFF_HH + off) = hi;
                    *(uint32_t*)(sm + OFF_HL + off) = lo;
                    hi = pack_split(fmaxf(acc[2] + bv0, 0.f), fmaxf(acc[3] + bv1, 0.f), lo);
                    *(uint32_t*)(sm + OFF_HH + off + 8 * 144) = hi;
                    *(uint32_t*)(sm + OFF_HL + off + 8 * 144) = lo;
                }
                __syncwarp();

                // ---- GEMM2: outAcc += H @ W2[c*64 : +64, :] ----
                uint32_t HAh[4][4], HAl[4][4];
                {
                    uint32_t base = sb + (uint32_t)(wid * 16 + l15) * 144 + (uint32_t)(lane >> 4) * 16;
                    #pragma unroll
                    for (int k = 0; k < 4; k++) {
                        ldsm_x4(HAh[k], base + OFF_HH + k * 32);
                        ldsm_x4(HAl[k], base + OFF_HL + k * 32);
                    }
                }
                #pragma unroll
                for (int n = 0; n < 8; n++) {
                    #pragma unroll
                    for (int k = 0; k < 4; k++) {
                        uint32_t Bh[2], Bl[2];
                        uint32_t ba = sb + (uint32_t)(c * 64 + k * 16 + l15) * 144 + (uint32_t)(n * 8) * 2;
                        ldsm_x2t(Bh, ba + OFF_W2H);
                        ldsm_x2t(Bl, ba + OFF_W2L);
                        mma16816(outAcc[n], HAh[k], Bh);
                        mma16816(outAcc[n], HAh[k], Bl);
                        mma16816(outAcc[n], HAl[k], Bh);
                    }
                }
                __syncwarp();   // H safe to overwrite next chunk
            }

            // ---- tile epilogue ----
            int row0 = t * 128 + wid * 16 + rr;
            if (b == 0) {
                float* p0 = g_part + (size_t)row0 * 64 + cc;
                float* p1 = p0 + 8 * 64;
                #pragma unroll
                for (int n = 0; n < 8; n++) {
                    *(float2*)(p0 + n * 8) = make_float2(outAcc[n][0], outAcc[n][1]);
                    *(float2*)(p1 + n * 8) = make_float2(outAcc[n][2], outAcc[n][3]);
                }
            } else {
                #pragma unroll
                for (int half = 0; half < 2; half++) {
                    int gr = row0 + half * 8;
                    if (gr < TT) {
                        const float* pp = g_part + (size_t)gr * 64 + cc;
                        float* po = out + (size_t)gr * 64 + cc;
                        #pragma unroll
                        for (int n = 0; n < 8; n++) {
                            float2 pv = *(const float2*)(pp + n * 8);
                            float o0 = fmaxf(outAcc[n][half * 2]     + pv.x + sb2c[n * 8 + cc],     0.f);
                            float o1 = fmaxf(outAcc[n][half * 2 + 1] + pv.y + sb2c[n * 8 + cc + 1], 0.f);
                            *(float2*)(po + n * 8) = make_float2(o0, o1);
                        }
                    }
                }
            }
            __syncwarp();   // X safe to overwrite next tile
        }
    }
}

// ================= launch =================
extern "C" void kernel_launch(void* const* d_in, const int* in_sizes, int n_in,
                              void* d_out, int out_size) {
    const float* h       = (const float*)d_in[0];
    const float* cell    = (const float*)d_in[1];
    const float* attn    = (const float*)d_in[2];
    const float* Wn1     = (const float*)d_in[3];
    const float* bn1     = (const float*)d_in[4];
    const float* Wn2     = (const float*)d_in[5];
    const float* bn2     = (const float*)d_in[6];
    const float* Ws1     = (const float*)d_in[7];
    const float* bs1     = (const float*)d_in[8];
    const float* Ws2     = (const float*)d_in[9];
    const float* bs2     = (const float*)d_in[10];
    const int*   src     = (const int*)d_in[11];
    const int*   dst     = (const int*)d_in[12];
    const int*   targets = (const int*)d_in[13];
    float* out = (float*)d_out;

    cudaFuncSetAttribute(k_mlp2, cudaFuncAttributeMaxDynamicSharedMemorySize, SMEM_TOTAL);

    k_init<<<(MAXSLOT * DD / 4 + 255) / 256, 256>>>();
    k_score<<<(NN * 32 + 255) / 256, 256>>>(h, attn);
    k_mark<<<(TT + 255) / 256, 256>>>(targets);
    k_edge1<<<(EE + 255) / 256, 256>>>(src, dst);   // launch #4 -> profiled
    k_wsplit<<<256, 256>>>(Ws1, Wn1, Ws2, Wn2);
    k_edge2<<<2048, 256>>>();
    k_edge3<<<4096, 256>>>(h);
    k_mlp2<<<GRID_MLP, 256, SMEM_TOTAL>>>(cell, bn1, bn2, bs1, bs2, targets, out);
}

// round 8
// speedup vs baseline: 1.8952x; 1.5630x over previous
#include <cuda_runtime.h>
#include <cuda_bf16.h>
#include <math.h>
#include <stdint.h>

#define NN 500000
#define EE 2000000
#define DD 64
#define HIDN 256
#define TT 100000
#define MAXSLOT 100000
#define NT256 391                 // ceil(100000/256)
#define GRID_MLP 148

// ================= static scratch =================
__device__ float g_s[NN];
__device__ int   g_slot[NN];
__device__ int   g_relSrc[EE];
__device__ int   g_relSlot[EE];
__device__ int   g_csr[EE];
__device__ int   g_deg[MAXSLOT];
__device__ int   g_off[MAXSLOT];
__device__ int   g_cur[MAXSLOT];
__device__ int   g_blk[512];
__device__ int   g_blkOff[512];
__device__ float g_hneigh[MAXSLOT * DD];
__device__ int   g_cnt[2];
// pre-split weights (bf16 hi/lo): g_W1s[b][p]: [64 k][256 n], g_W2s[b][p]: [256 k][64 n]
__device__ __align__(16) unsigned short g_W1s[2][2][64 * 256];
__device__ __align__(16) unsigned short g_W2s[2][2][256 * 64];
__device__ float g_part[(size_t)NT256 * 256 * 64];   // branch-0 partials (25.6MB)

// ================= PTX helpers =================
__device__ __forceinline__ uint32_t smem_u32(const void* p) {
    uint32_t a;
    asm("{ .reg .u64 t; cvta.to.shared.u64 t, %1; cvt.u32.u64 %0, t; }" : "=r"(a) : "l"(p));
    return a;
}
__device__ __forceinline__ void ldsm_x2t(uint32_t* r, uint32_t addr) {
    asm volatile("ldmatrix.sync.aligned.m8n8.x2.trans.shared.b16 {%0,%1}, [%2];"
        : "=r"(r[0]), "=r"(r[1]) : "r"(addr));
}
__device__ __forceinline__ void mma16816(float* c, const uint32_t* a, const uint32_t* b) {
    asm volatile("mma.sync.aligned.m16n8k16.row.col.f32.bf16.bf16.f32 "
        "{%0,%1,%2,%3}, {%4,%5,%6,%7}, {%8,%9}, {%0,%1,%2,%3};"
        : "+f"(c[0]), "+f"(c[1]), "+f"(c[2]), "+f"(c[3])
        : "r"(a[0]), "r"(a[1]), "r"(a[2]), "r"(a[3]), "r"(b[0]), "r"(b[1]));
}
__device__ __forceinline__ uint32_t pack_split(float x0, float x1, uint32_t& lo_out) {
    __nv_bfloat16 h0 = __float2bfloat16_rn(x0);
    __nv_bfloat16 h1 = __float2bfloat16_rn(x1);
    __nv_bfloat16 l0 = __float2bfloat16_rn(x0 - __bfloat162float(h0));
    __nv_bfloat16 l1 = __float2bfloat16_rn(x1 - __bfloat162float(h1));
    lo_out = ((uint32_t)__bfloat16_as_ushort(l1) << 16) | __bfloat16_as_ushort(l0);
    return ((uint32_t)__bfloat16_as_ushort(h1) << 16) | __bfloat16_as_ushort(h0);
}

// ================= init =================
__global__ void k_init() {
    int i = blockIdx.x * blockDim.x + threadIdx.x;
    if (i < NN) g_slot[i] = -1;
    if (i < MAXSLOT) g_deg[i] = 0;
    if (i < 2) g_cnt[i] = 0;
}

// ================= weight split prep =================
__global__ void k_wsplit(const float* __restrict__ Ws1, const float* __restrict__ Wn1,
                         const float* __restrict__ Ws2, const float* __restrict__ Wn2) {
    int gid = blockIdx.x * blockDim.x + threadIdx.x;
    if (gid >= 65536) return;
    int half = gid >> 15;
    int b = (gid >> 14) & 1;
    int e = gid & 16383;
    if (half == 0) {
        const float* W1 = b ? Wn1 : Ws1;   // [64][256]
        float v = W1[e];
        __nv_bfloat16 hi = __float2bfloat16_rn(v);
        __nv_bfloat16 lo = __float2bfloat16_rn(v - __bfloat162float(hi));
        g_W1s[b][0][e] = __bfloat16_as_ushort(hi);
        g_W1s[b][1][e] = __bfloat16_as_ushort(lo);
    } else {
        const float* W2 = b ? Wn2 : Ws2;   // [256][64]
        float v = W2[e];
        __nv_bfloat16 hi = __float2bfloat16_rn(v);
        __nv_bfloat16 lo = __float2bfloat16_rn(v - __bfloat162float(hi));
        g_W2s[b][0][e] = __bfloat16_as_ushort(hi);
        g_W2s[b][1][e] = __bfloat16_as_ushort(lo);
    }
}

// ================= per-node attention score =================
__global__ void k_score(const float* __restrict__ h, const float* __restrict__ attn) {
    int w = (blockIdx.x * blockDim.x + threadIdx.x) >> 5;
    int lane = threadIdx.x & 31;
    if (w >= NN) return;
    const float* hr = h + (size_t)w * DD;
    float v = hr[lane] * __ldg(attn + lane) + hr[lane + 32] * __ldg(attn + lane + 32);
    #pragma unroll
    for (int o = 16; o; o >>= 1) v += __shfl_xor_sync(0xffffffffu, v, o);
    if (lane == 0) g_s[w] = fmaxf(v, 0.f);
}

// ================= mark targets / compact slots =================
__global__ void k_mark(const int* __restrict__ targets) {
    int t = blockIdx.x * blockDim.x + threadIdx.x;
    int node = -1;
    bool claim = false;
    if (t < TT) {
        node = targets[t];
        claim = (atomicCAS(&g_slot[node], -1, -2) == -1);
    }
    unsigned mask = __ballot_sync(0xffffffffu, claim);
    if (mask) {
        int lane = threadIdx.x & 31;
        int leader = __ffs(mask) - 1;
        int base = 0;
        if (lane == leader) base = atomicAdd(&g_cnt[0], __popc(mask));
        base = __shfl_sync(0xffffffffu, base, leader);
        if (claim) {
            int rank = __popc(mask & ((1u << lane) - 1u));
            atomicExch(&g_slot[node], base + rank);
        }
    }
}

// ================= edge pass: compact relevant edges + degree histogram =================
__global__ void k_edge1(const int* __restrict__ src, const int* __restrict__ dst) {
    __shared__ int sWarp[8];
    __shared__ int sBase;
    int e = blockIdx.x * blockDim.x + threadIdx.x;
    int lane = threadIdx.x & 31, wid = threadIdx.x >> 5;
    int slot = -1, sn = 0;
    if (e < EE) {
        slot = g_slot[dst[e]];
        if (slot >= 0) {
            sn = src[e];
            atomicAdd(&g_deg[slot], 1);
        }
    }
    bool rel = (slot >= 0);
    unsigned mask = __ballot_sync(0xffffffffu, rel);
    if (lane == 0) sWarp[wid] = __popc(mask);
    __syncthreads();
    if (threadIdx.x == 0) {
        int tot = 0;
        #pragma unroll
        for (int w = 0; w < 8; w++) { int c = sWarp[w]; sWarp[w] = tot; tot += c; }
        sBase = tot ? atomicAdd(&g_cnt[1], tot) : 0;
    }
    __syncthreads();
    if (rel) {
        int j = sBase + sWarp[wid] + __popc(mask & ((1u << lane) - 1u));
        g_relSrc[j] = sn;
        g_relSlot[j] = slot;
    }
}

// ================= scan (3 kernels) =================
__global__ void k_scanA() {   // 391 blocks x 256: block sums
    __shared__ int s[256];
    int i = blockIdx.x * 256 + threadIdx.x;
    s[threadIdx.x] = (i < MAXSLOT) ? g_deg[i] : 0;
    __syncthreads();
    #pragma unroll
    for (int o = 128; o; o >>= 1) {
        if (threadIdx.x < o) s[threadIdx.x] += s[threadIdx.x + o];
        __syncthreads();
    }
    if (threadIdx.x == 0) g_blk[blockIdx.x] = s[0];
}
__global__ void k_scanB() {   // 1 block x 512: exclusive scan of 391 block sums
    __shared__ int s[512];
    int v = (threadIdx.x < NT256) ? g_blk[threadIdx.x] : 0;
    s[threadIdx.x] = v;
    __syncthreads();
    #pragma unroll
    for (int o = 1; o < 512; o <<= 1) {
        int add = (threadIdx.x >= o) ? s[threadIdx.x - o] : 0;
        __syncthreads();
        s[threadIdx.x] += add;
        __syncthreads();
    }
    g_blkOff[threadIdx.x] = s[threadIdx.x] - v;
}
__global__ void k_scanC() {   // 391 blocks x 256: local exclusive scan + base
    __shared__ int s[256];
    int i = blockIdx.x * 256 + threadIdx.x;
    int v = (i < MAXSLOT) ? g_deg[i] : 0;
    s[threadIdx.x] = v;
    __syncthreads();
    #pragma unroll
    for (int o = 1; o < 256; o <<= 1) {
        int add = (threadIdx.x >= o) ? s[threadIdx.x - o] : 0;
        __syncthreads();
        s[threadIdx.x] += add;
        __syncthreads();
    }
    if (i < MAXSLOT) {
        int off = g_blkOff[blockIdx.x] + s[threadIdx.x] - v;
        g_off[i] = off;
        g_cur[i] = off;
    }
}

// ================= scatter into CSR =================
__global__ void k_scatter() {
    int cnt = g_cnt[1];
    int stride = gridDim.x * blockDim.x;
    for (int j = blockIdx.x * blockDim.x + threadIdx.x; j < cnt; j += stride) {
        int slot = g_relSlot[j];
        int pos = atomicAdd(&g_cur[slot], 1);
        g_csr[pos] = g_relSrc[j];
    }
}

// ================= gather: softmax + weighted sum per slot (no atomics) =================
__global__ void k_gather(const float* __restrict__ h) {
    int gw = (blockIdx.x * blockDim.x + threadIdx.x) >> 5;
    int lane = threadIdx.x & 31;
    if (gw >= MAXSLOT) return;
    int nslot = g_cnt[0];
    if (gw >= nslot) return;
    int o0 = g_off[gw];
    int deg = g_deg[gw];
    // online softmax over segment (scores >= 0, empty -> m=0 matches reference)
    float m = 0.f, den = 0.f;
    for (int j = 0; j < deg; j++) {
        float sv = g_s[g_csr[o0 + j]];
        if (sv > m) { den *= expf(m - sv); m = sv; }
        den += expf(sv - m);
    }
    float inv = (deg > 0) ? (1.f / den) : 0.f;
    float a0 = 0.f, a1 = 0.f;
    for (int j = 0; j < deg; j++) {
        int sn = g_csr[o0 + j];
        float w = expf(g_s[sn] - m) * inv;
        const float* hr = h + (size_t)sn * DD;
        a0 += w * hr[lane];
        a1 += w * hr[lane + 32];
    }
    g_hneigh[gw * DD + lane]      = a0;
    g_hneigh[gw * DD + lane + 32] = a1;
}

// ================= MMA fused dual-MLP (weights-only SMEM, 256-row tiles) =================
#define OFF_W1H 0u          // [64][264] bf16, stride 528B
#define OFF_W1L 33792u
#define OFF_W2H 67584u      // [256][72] bf16, stride 144B
#define OFF_W2L 104448u
#define OFF_SB1 141312u     // [2][256] f32
#define OFF_SB2 143360u     // [64] f32
#define SMEM_TOTAL 143616u

__global__ void __launch_bounds__(256, 1) k_mlp3(
    const float* __restrict__ cell,
    const float* __restrict__ bn1, const float* __restrict__ bn2,
    const float* __restrict__ bs1, const float* __restrict__ bs2,
    const int* __restrict__ targets, float* __restrict__ out)
{
    extern __shared__ __align__(128) unsigned char sm[];
    uint32_t sb = smem_u32(sm);
    int tid = threadIdx.x;
    int wid = tid >> 5, lane = tid & 31;
    int l15 = lane & 15;
    int r_in = lane >> 2;          // fragment row within 8
    int c2 = (lane & 3) * 2;       // fragment col pair

    float* sb1  = (float*)(sm + OFF_SB1);
    float* sb2c = (float*)(sm + OFF_SB2);
    sb1[tid]       = __ldg(bs1 + tid);
    sb1[256 + tid] = __ldg(bn1 + tid);
    if (tid < 64) sb2c[tid] = __ldg(bs2 + tid) + __ldg(bn2 + tid);

    #pragma unroll 1
    for (int b = 0; b < 2; b++) {
        __syncthreads();   // all warps done with previous branch's weights
        #pragma unroll 1
        for (int i = tid; i < 2048; i += 256) {
            int row = i >> 5, q = i & 31;
            *(float4*)(sm + OFF_W1H + row * 528 + q * 16) =
                ((const float4*)(g_W1s[b][0] + row * 256))[q];
            *(float4*)(sm + OFF_W1L + row * 528 + q * 16) =
                ((const float4*)(g_W1s[b][1] + row * 256))[q];
        }
        #pragma unroll 1
        for (int i = tid; i < 2048; i += 256) {
            int row = i >> 3, q = i & 7;
            *(float4*)(sm + OFF_W2H + row * 144 + q * 16) =
                ((const float4*)(g_W2s[b][0] + row * 64))[q];
            *(float4*)(sm + OFF_W2L + row * 144 + q * 16) =
                ((const float4*)(g_W2s[b][1] + row * 64))[q];
        }
        __syncthreads();

        #pragma unroll 1
        for (int t = blockIdx.x; t < NT256; t += GRID_MLP) {
            // ---- build X A-fragments directly from global (no SMEM) ----
            uint32_t XAh[2][4][4], XAl[2][4][4];
            #pragma unroll
            for (int rs = 0; rs < 2; rs++) {
                int gr0 = t * 256 + wid * 32 + rs * 16 + r_in;
                int gr1 = gr0 + 8;
                const float* p0 = 0;
                const float* p1 = 0;
                if (gr0 < TT) {
                    int node = __ldg(targets + gr0);
                    p0 = b ? (g_hneigh + (size_t)g_slot[node] * 64)
                           : (cell + (size_t)node * 64);
                }
                if (gr1 < TT) {
                    int node = __ldg(targets + gr1);
                    p1 = b ? (g_hneigh + (size_t)g_slot[node] * 64)
                           : (cell + (size_t)node * 64);
                }
                #pragma unroll
                for (int kf = 0; kf < 4; kf++) {
                    int col = kf * 16 + c2;
                    float2 z = make_float2(0.f, 0.f);
                    float2 v00 = p0 ? *(const float2*)(p0 + col)     : z;
                    float2 v01 = p0 ? *(const float2*)(p0 + col + 8) : z;
                    float2 v10 = p1 ? *(const float2*)(p1 + col)     : z;
                    float2 v11 = p1 ? *(const float2*)(p1 + col + 8) : z;
                    XAh[rs][kf][0] = pack_split(v00.x, v00.y, XAl[rs][kf][0]);
                    XAh[rs][kf][1] = pack_split(v10.x, v10.y, XAl[rs][kf][1]);
                    XAh[rs][kf][2] = pack_split(v01.x, v01.y, XAl[rs][kf][2]);
                    XAh[rs][kf][3] = pack_split(v11.x, v11.y, XAl[rs][kf][3]);
                }
            }

            float outAcc[2][8][4];
            #pragma unroll
            for (int rs = 0; rs < 2; rs++)
                #pragma unroll
                for (int n = 0; n < 8; n++)
                    #pragma unroll
                    for (int q = 0; q < 4; q++) outAcc[rs][n][q] = 0.f;

            #pragma unroll 1
            for (int c = 0; c < 4; c++) {
                // ---- GEMM1 chunk -> H A-fragments in registers ----
                uint32_t HAh[2][4][4], HAl[2][4][4];
                #pragma unroll
                for (int n = 0; n < 8; n++) {
                    float a0[4] = {0.f, 0.f, 0.f, 0.f};
                    float a1[4] = {0.f, 0.f, 0.f, 0.f};
                    #pragma unroll
                    for (int k = 0; k < 4; k++) {
                        uint32_t Bh[2], Bl[2];
                        uint32_t ba = sb + (uint32_t)(k * 16 + l15) * 528
                                         + (uint32_t)(c * 64 + n * 8) * 2;
                        ldsm_x2t(Bh, ba + OFF_W1H);
                        ldsm_x2t(Bl, ba + OFF_W1L);
                        mma16816(a0, XAh[0][k], Bh);
                        mma16816(a0, XAh[0][k], Bl);
                        mma16816(a0, XAl[0][k], Bh);
                        mma16816(a1, XAh[1][k], Bh);
                        mma16816(a1, XAh[1][k], Bl);
                        mma16816(a1, XAl[1][k], Bh);
                    }
                    // bias + relu + bf16 split -> GEMM2 A-frag registers
                    int hc = c * 64 + n * 8 + c2;
                    float bv0 = sb1[b * 256 + hc];
                    float bv1 = sb1[b * 256 + hc + 1];
                    int tt = n >> 1, odd = (n & 1) * 2;
                    HAh[0][tt][odd] = pack_split(fmaxf(a0[0] + bv0, 0.f),
                                                 fmaxf(a0[1] + bv1, 0.f), HAl[0][tt][odd]);
                    HAh[0][tt][odd + 1] = pack_split(fmaxf(a0[2] + bv0, 0.f),
                                                     fmaxf(a0[3] + bv1, 0.f), HAl[0][tt][odd + 1]);
                    HAh[1][tt][odd] = pack_split(fmaxf(a1[0] + bv0, 0.f),
                                                 fmaxf(a1[1] + bv1, 0.f), HAl[1][tt][odd]);
                    HAh[1][tt][odd + 1] = pack_split(fmaxf(a1[2] + bv0, 0.f),
                                                     fmaxf(a1[3] + bv1, 0.f), HAl[1][tt][odd + 1]);
                }

                // ---- GEMM2 chunk: outAcc += H @ W2[c*64:+64, :] ----
                #pragma unroll
                for (int n = 0; n < 8; n++) {
                    #pragma unroll
                    for (int k = 0; k < 4; k++) {
                        uint32_t Bh[2], Bl[2];
                        uint32_t ba = sb + (uint32_t)(c * 64 + k * 16 + l15) * 144
                                         + (uint32_t)(n * 8) * 2;
                        ldsm_x2t(Bh, ba + OFF_W2H);
                        ldsm_x2t(Bl, ba + OFF_W2L);
                        mma16816(outAcc[0][n], HAh[0][k], Bh);
                        mma16816(outAcc[0][n], HAh[0][k], Bl);
                        mma16816(outAcc[0][n], HAl[0][k], Bh);
                        mma16816(outAcc[1][n], HAh[1][k], Bh);
                        mma16816(outAcc[1][n], HAh[1][k], Bl);
                        mma16816(outAcc[1][n], HAl[1][k], Bh);
                    }
                }
            }

            // ---- tile epilogue ----
            #pragma unroll
            for (int rs = 0; rs < 2; rs++) {
                int gr0 = t * 256 + wid * 32 + rs * 16 + r_in;
                int gr1 = gr0 + 8;
                if (b == 0) {
                    float* q0 = g_part + (size_t)gr0 * 64 + c2;
                    float* q1 = g_part + (size_t)gr1 * 64 + c2;
                    #pragma unroll
                    for (int n = 0; n < 8; n++) {
                        *(float2*)(q0 + n * 8) = make_float2(outAcc[rs][n][0], outAcc[rs][n][1]);
                        *(float2*)(q1 + n * 8) = make_float2(outAcc[rs][n][2], outAcc[rs][n][3]);
                    }
                } else {
                    if (gr0 < TT) {
                        const float* pp = g_part + (size_t)gr0 * 64 + c2;
                        float* po = out + (size_t)gr0 * 64 + c2;
                        #pragma unroll
                        for (int n = 0; n < 8; n++) {
                            float2 pv = *(const float2*)(pp + n * 8);
                            *(float2*)(po + n * 8) = make_float2(
                                fmaxf(outAcc[rs][n][0] + pv.x + sb2c[n * 8 + c2], 0.f),
                                fmaxf(outAcc[rs][n][1] + pv.y + sb2c[n * 8 + c2 + 1], 0.f));
                        }
                    }
                    if (gr1 < TT) {
                        const float* pp = g_part + (size_t)gr1 * 64 + c2;
                        float* po = out + (size_t)gr1 * 64 + c2;
                        #pragma unroll
                        for (int n = 0; n < 8; n++) {
                            float2 pv = *(const float2*)(pp + n * 8);
                            *(float2*)(po + n * 8) = make_float2(
                                fmaxf(outAcc[rs][n][2] + pv.x + sb2c[n * 8 + c2], 0.f),
                                fmaxf(outAcc[rs][n][3] + pv.y + sb2c[n * 8 + c2 + 1], 0.f));
                        }
                    }
                }
            }
        }
    }
}

// ================= launch =================
extern "C" void kernel_launch(void* const* d_in, const int* in_sizes, int n_in,
                              void* d_out, int out_size) {
    const float* h       = (const float*)d_in[0];
    const float* cell    = (const float*)d_in[1];
    const float* attn    = (const float*)d_in[2];
    const float* Wn1     = (const float*)d_in[3];
    const float* bn1     = (const float*)d_in[4];
    const float* Wn2     = (const float*)d_in[5];
    const float* bn2     = (const float*)d_in[6];
    const float* Ws1     = (const float*)d_in[7];
    const float* bs1     = (const float*)d_in[8];
    const float* Ws2     = (const float*)d_in[9];
    const float* bs2     = (const float*)d_in[10];
    const int*   src     = (const int*)d_in[11];
    const int*   dst     = (const int*)d_in[12];
    const int*   targets = (const int*)d_in[13];
    float* out = (float*)d_out;

    cudaFuncSetAttribute(k_mlp3, cudaFuncAttributeMaxDynamicSharedMemorySize, SMEM_TOTAL);

    k_init<<<(NN + 255) / 256, 256>>>();
    k_score<<<(NN * 32 + 255) / 256, 256>>>(h, attn);
    k_mark<<<(TT + 255) / 256, 256>>>(targets);
    k_edge1<<<(EE + 255) / 256, 256>>>(src, dst);
    k_wsplit<<<256, 256>>>(Ws1, Wn1, Ws2, Wn2);
    k_scanA<<<NT256, 256>>>();
    k_scanB<<<1, 512>>>();
    k_scanC<<<NT256, 256>>>();
    k_scatter<<<2048, 256>>>();
    k_gather<<<(MAXSLOT + 7) / 8, 256>>>(h);
    k_mlp3<<<GRID_MLP, 256, SMEM_TOTAL>>>(cell, bn1, bn2, bs1, bs2, targets, out);
}

// round 10
// speedup vs baseline: 2.1724x; 1.1463x over previous
#include <cuda_runtime.h>
#include <cuda_bf16.h>
#include <math.h>
#include <stdint.h>

#define NN 500000
#define EE 2000000
#define DD 64
#define HIDN 256
#define TT 100000
#define MAXSLOT 100000
#define NT256 391                 // ceil(100000/256)
#define GRID_MLP 148

// ================= static scratch =================
__device__ int   g_slot[NN];
__device__ int   g_relSrc[EE];
__device__ int   g_relSlot[EE];
__device__ int   g_csr[EE];
__device__ int   g_deg[MAXSLOT];
__device__ int   g_off[MAXSLOT];
__device__ int   g_cur[MAXSLOT];
__device__ int   g_blk[512];
__device__ int   g_blkOff[512];
__device__ float g_hneigh[MAXSLOT * DD];
__device__ int   g_cnt[2];
// pre-split weights (bf16 hi/lo): g_W1s[b][p]: [64 k][256 n], g_W2s[b][p]: [256 k][64 n]
__device__ __align__(16) unsigned short g_W1s[2][2][64 * 256];
__device__ __align__(16) unsigned short g_W2s[2][2][256 * 64];

// ================= PTX helpers =================
__device__ __forceinline__ uint32_t smem_u32(const void* p) {
    uint32_t a;
    asm("{ .reg .u64 t; cvta.to.shared.u64 t, %1; cvt.u32.u64 %0, t; }" : "=r"(a) : "l"(p));
    return a;
}
__device__ __forceinline__ void ldsm_x2t(uint32_t* r, uint32_t addr) {
    asm volatile("ldmatrix.sync.aligned.m8n8.x2.trans.shared.b16 {%0,%1}, [%2];"
        : "=r"(r[0]), "=r"(r[1]) : "r"(addr));
}
__device__ __forceinline__ void mma16816(float* c, const uint32_t* a, const uint32_t* b) {
    asm volatile("mma.sync.aligned.m16n8k16.row.col.f32.bf16.bf16.f32 "
        "{%0,%1,%2,%3}, {%4,%5,%6,%7}, {%8,%9}, {%0,%1,%2,%3};"
        : "+f"(c[0]), "+f"(c[1]), "+f"(c[2]), "+f"(c[3])
        : "r"(a[0]), "r"(a[1]), "r"(a[2]), "r"(a[3]), "r"(b[0]), "r"(b[1]));
}
__device__ __forceinline__ uint32_t pack_split(float x0, float x1, uint32_t& lo_out) {
    __nv_bfloat16 h0 = __float2bfloat16_rn(x0);
    __nv_bfloat16 h1 = __float2bfloat16_rn(x1);
    __nv_bfloat16 l0 = __float2bfloat16_rn(x0 - __bfloat162float(h0));
    __nv_bfloat16 l1 = __float2bfloat16_rn(x1 - __bfloat162float(h1));
    lo_out = ((uint32_t)__bfloat16_as_ushort(l1) << 16) | __bfloat16_as_ushort(l0);
    return ((uint32_t)__bfloat16_as_ushort(h1) << 16) | __bfloat16_as_ushort(h0);
}

// ================= init =================
__global__ void k_init() {
    int i = blockIdx.x * blockDim.x + threadIdx.x;
    if (i < NN) g_slot[i] = -1;
    if (i < MAXSLOT) g_deg[i] = 0;
    if (i < 2) g_cnt[i] = 0;
}

// ================= weight split prep =================
__global__ void k_wsplit(const float* __restrict__ Ws1, const float* __restrict__ Wn1,
                         const float* __restrict__ Ws2, const float* __restrict__ Wn2) {
    int gid = blockIdx.x * blockDim.x + threadIdx.x;
    if (gid >= 65536) return;
    int half = gid >> 15;
    int b = (gid >> 14) & 1;
    int e = gid & 16383;
    if (half == 0) {
        const float* W1 = b ? Wn1 : Ws1;   // [64][256]
        float v = W1[e];
        __nv_bfloat16 hi = __float2bfloat16_rn(v);
        __nv_bfloat16 lo = __float2bfloat16_rn(v - __bfloat162float(hi));
        g_W1s[b][0][e] = __bfloat16_as_ushort(hi);
        g_W1s[b][1][e] = __bfloat16_as_ushort(lo);
    } else {
        const float* W2 = b ? Wn2 : Ws2;   // [256][64]
        float v = W2[e];
        __nv_bfloat16 hi = __float2bfloat16_rn(v);
        __nv_bfloat16 lo = __float2bfloat16_rn(v - __bfloat162float(hi));
        g_W2s[b][0][e] = __bfloat16_as_ushort(hi);
        g_W2s[b][1][e] = __bfloat16_as_ushort(lo);
    }
}

// ================= mark targets / compact slots =================
__global__ void k_mark(const int* __restrict__ targets) {
    int t = blockIdx.x * blockDim.x + threadIdx.x;
    int node = -1;
    bool claim = false;
    if (t < TT) {
        node = targets[t];
        claim = (atomicCAS(&g_slot[node], -1, -2) == -1);
    }
    unsigned mask = __ballot_sync(0xffffffffu, claim);
    if (mask) {
        int lane = threadIdx.x & 31;
        int leader = __ffs(mask) - 1;
        int base = 0;
        if (lane == leader) base = atomicAdd(&g_cnt[0], __popc(mask));
        base = __shfl_sync(0xffffffffu, base, leader);
        if (claim) {
            int rank = __popc(mask & ((1u << lane) - 1u));
            atomicExch(&g_slot[node], base + rank);
        }
    }
}

// ================= edge pass: compact relevant edges + degree histogram =================
__global__ void k_edge1(const int* __restrict__ src, const int* __restrict__ dst) {
    __shared__ int sWarp[8];
    __shared__ int sBase;
    int e = blockIdx.x * blockDim.x + threadIdx.x;
    int lane = threadIdx.x & 31, wid = threadIdx.x >> 5;
    int slot = -1, sn = 0;
    if (e < EE) {
        slot = g_slot[dst[e]];
        if (slot >= 0) {
            sn = src[e];
            atomicAdd(&g_deg[slot], 1);
        }
    }
    bool rel = (slot >= 0);
    unsigned mask = __ballot_sync(0xffffffffu, rel);
    if (lane == 0) sWarp[wid] = __popc(mask);
    __syncthreads();
    if (threadIdx.x == 0) {
        int tot = 0;
        #pragma unroll
        for (int w = 0; w < 8; w++) { int c = sWarp[w]; sWarp[w] = tot; tot += c; }
        sBase = tot ? atomicAdd(&g_cnt[1], tot) : 0;
    }
    __syncthreads();
    if (rel) {
        int j = sBase + sWarp[wid] + __popc(mask & ((1u << lane) - 1u));
        g_relSrc[j] = sn;
        g_relSlot[j] = slot;
    }
}

// ================= scan (3 kernels) =================
__global__ void k_scanA() {
    __shared__ int s[256];
    int i = blockIdx.x * 256 + threadIdx.x;
    s[threadIdx.x] = (i < MAXSLOT) ? g_deg[i] : 0;
    __syncthreads();
    #pragma unroll
    for (int o = 128; o; o >>= 1) {
        if (threadIdx.x < o) s[threadIdx.x] += s[threadIdx.x + o];
        __syncthreads();
    }
    if (threadIdx.x == 0) g_blk[blockIdx.x] = s[0];
}
__global__ void k_scanB() {
    __shared__ int s[512];
    int v = (threadIdx.x < NT256) ? g_blk[threadIdx.x] : 0;
    s[threadIdx.x] = v;
    __syncthreads();
    #pragma unroll
    for (int o = 1; o < 512; o <<= 1) {
        int add = (threadIdx.x >= o) ? s[threadIdx.x - o] : 0;
        __syncthreads();
        s[threadIdx.x] += add;
        __syncthreads();
    }
    g_blkOff[threadIdx.x] = s[threadIdx.x] - v;
}
__global__ void k_scanC() {
    __shared__ int s[256];
    int i = blockIdx.x * 256 + threadIdx.x;
    int v = (i < MAXSLOT) ? g_deg[i] : 0;
    s[threadIdx.x] = v;
    __syncthreads();
    #pragma unroll
    for (int o = 1; o < 256; o <<= 1) {
        int add = (threadIdx.x >= o) ? s[threadIdx.x - o] : 0;
        __syncthreads();
        s[threadIdx.x] += add;
        __syncthreads();
    }
    if (i < MAXSLOT) {
        int off = g_blkOff[blockIdx.x] + s[threadIdx.x] - v;
        g_off[i] = off;
        g_cur[i] = off;
    }
}

// ================= scatter into CSR =================
__global__ void k_scatter() {
    int cnt = g_cnt[1];
    int stride = gridDim.x * blockDim.x;
    for (int j = blockIdx.x * blockDim.x + threadIdx.x; j < cnt; j += stride) {
        int slot = g_relSlot[j];
        int pos = atomicAdd(&g_cur[slot], 1);
        g_csr[pos] = g_relSrc[j];
    }
}

// ====== gather: fused score + softmax + weighted sum per slot (no atomics) ======
__global__ void k_gather(const float* __restrict__ h, const float* __restrict__ attn) {
    int gw = (blockIdx.x * blockDim.x + threadIdx.x) >> 5;
    int lane = threadIdx.x & 31;
    if (gw >= MAXSLOT) return;
    if (gw >= g_cnt[0]) return;
    int o0 = g_off[gw];
    int deg = g_deg[gw];
    float aw0 = __ldg(attn + lane);
    float aw1 = __ldg(attn + lane + 32);
    // pass 1: scores inline (relu(h.attn)), online max/denominator
    float m = 0.f, den = 0.f;
    for (int j = 0; j < deg; j++) {
        int sn = g_csr[o0 + j];
        const float* hr = h + (size_t)sn * DD;
        float d = hr[lane] * aw0 + hr[lane + 32] * aw1;
        #pragma unroll
        for (int o = 16; o; o >>= 1) d += __shfl_xor_sync(0xffffffffu, d, o);
        float sv = fmaxf(d, 0.f);
        if (sv > m) { den *= expf(m - sv); m = sv; }
        den += expf(sv - m);
    }
    float inv = (deg > 0) ? (1.f / den) : 0.f;
    // pass 2: weighted sum (h rows warm in L1)
    float a0 = 0.f, a1 = 0.f;
    for (int j = 0; j < deg; j++) {
        int sn = g_csr[o0 + j];
        const float* hr = h + (size_t)sn * DD;
        float v0 = hr[lane], v1 = hr[lane + 32];
        float d = v0 * aw0 + v1 * aw1;
        #pragma unroll
        for (int o = 16; o; o >>= 1) d += __shfl_xor_sync(0xffffffffu, d, o);
        float w = expf(fmaxf(d, 0.f) - m) * inv;
        a0 += w * v0;
        a1 += w * v1;
    }
    g_hneigh[gw * DD + lane]      = a0;
    g_hneigh[gw * DD + lane + 32] = a1;
}

// ========= MMA fused dual-MLP: single tile pass, branch-inner, reg-lean =========
#define OFF_W1H 0u          // [64][264] bf16, stride 528B
#define OFF_W1L 33792u
#define OFF_W2H 67584u      // [256][72] bf16, stride 144B
#define OFF_W2L 104448u
#define OFF_SB1 141312u     // [2][256] f32
#define OFF_SB2 143360u     // [64] f32
#define SMEM_TOTAL 143616u

__global__ void __launch_bounds__(256, 1) k_mlp4(
    const float* __restrict__ cell,
    const float* __restrict__ bn1, const float* __restrict__ bn2,
    const float* __restrict__ bs1, const float* __restrict__ bs2,
    const int* __restrict__ targets, float* __restrict__ out)
{
    extern __shared__ __align__(128) unsigned char sm[];
    uint32_t sb = smem_u32(sm);
    int tid = threadIdx.x;
    int wid = tid >> 5, lane = tid & 31;
    int l15 = lane & 15;
    int r_in = lane >> 2;          // fragment row within 8
    int c2 = (lane & 3) * 2;       // fragment col pair

    float* sb1  = (float*)(sm + OFF_SB1);
    float* sb2c = (float*)(sm + OFF_SB2);
    sb1[tid]       = __ldg(bs1 + tid);
    sb1[256 + tid] = __ldg(bn1 + tid);
    if (tid < 64) sb2c[tid] = __ldg(bs2 + tid) + __ldg(bn2 + tid);

    #pragma unroll 1
    for (int t = blockIdx.x; t < NT256; t += GRID_MLP) {
        float outAcc[2][8][4];
        #pragma unroll
        for (int rs = 0; rs < 2; rs++)
            #pragma unroll
            for (int n = 0; n < 8; n++)
                #pragma unroll
                for (int q = 0; q < 4; q++) outAcc[rs][n][q] = 0.f;

        #pragma unroll 1
        for (int b = 0; b < 2; b++) {
            // ---- (re)load this branch's weights into SMEM ----
            __syncthreads();   // all warps done with previous weights
            #pragma unroll 1
            for (int i = tid; i < 2048; i += 256) {
                int row = i >> 5, q = i & 31;
                *(float4*)(sm + OFF_W1H + row * 528 + q * 16) =
                    ((const float4*)(g_W1s[b][0] + row * 256))[q];
                *(float4*)(sm + OFF_W1L + row * 528 + q * 16) =
                    ((const float4*)(g_W1s[b][1] + row * 256))[q];
            }
            #pragma unroll 1
            for (int i = tid; i < 2048; i += 256) {
                int row = i >> 3, q = i & 7;
                *(float4*)(sm + OFF_W2H + row * 144 + q * 16) =
                    ((const float4*)(g_W2s[b][0] + row * 64))[q];
                *(float4*)(sm + OFF_W2L + row * 144 + q * 16) =
                    ((const float4*)(g_W2s[b][1] + row * 64))[q];
            }
            __syncthreads();

            // ---- build X A-fragments directly from global ----
            uint32_t XAh[2][4][4], XAl[2][4][4];
            #pragma unroll
            for (int rs = 0; rs < 2; rs++) {
                int gr0 = t * 256 + wid * 32 + rs * 16 + r_in;
                int gr1 = gr0 + 8;
                const float* p0 = 0;
                const float* p1 = 0;
                if (gr0 < TT) {
                    int node = __ldg(targets + gr0);
                    p0 = b ? (g_hneigh + (size_t)g_slot[node] * 64)
                           : (cell + (size_t)node * 64);
                }
                if (gr1 < TT) {
                    int node = __ldg(targets + gr1);
                    p1 = b ? (g_hneigh + (size_t)g_slot[node] * 64)
                           : (cell + (size_t)node * 64);
                }
                #pragma unroll
                for (int kf = 0; kf < 4; kf++) {
                    int col = kf * 16 + c2;
                    float2 z = make_float2(0.f, 0.f);
                    float2 v00 = p0 ? *(const float2*)(p0 + col)     : z;
                    float2 v01 = p0 ? *(const float2*)(p0 + col + 8) : z;
                    float2 v10 = p1 ? *(const float2*)(p1 + col)     : z;
                    float2 v11 = p1 ? *(const float2*)(p1 + col + 8) : z;
                    XAh[rs][kf][0] = pack_split(v00.x, v00.y, XAl[rs][kf][0]);
                    XAh[rs][kf][1] = pack_split(v10.x, v10.y, XAl[rs][kf][1]);
                    XAh[rs][kf][2] = pack_split(v01.x, v01.y, XAl[rs][kf][2]);
                    XAh[rs][kf][3] = pack_split(v11.x, v11.y, XAl[rs][kf][3]);
                }
            }

            #pragma unroll 1
            for (int c = 0; c < 4; c++) {
                // per k-fragment of H: GEMM1 for its 2 n-tiles, then GEMM2 immediately
                #pragma unroll
                for (int kk = 0; kk < 4; kk++) {
                    uint32_t HAh[2][4], HAl[2][4];
                    #pragma unroll
                    for (int nn = 0; nn < 2; nn++) {
                        int n = kk * 2 + nn;
                        float a0[4] = {0.f, 0.f, 0.f, 0.f};
                        float a1[4] = {0.f, 0.f, 0.f, 0.f};
                        #pragma unroll
                        for (int k = 0; k < 4; k++) {
                            uint32_t Bh[2], Bl[2];
                            uint32_t ba = sb + (uint32_t)(k * 16 + l15) * 528
                                             + (uint32_t)(c * 64 + n * 8) * 2;
                            ldsm_x2t(Bh, ba + OFF_W1H);
                            ldsm_x2t(Bl, ba + OFF_W1L);
                            mma16816(a0, XAh[0][k], Bh);
                            mma16816(a0, XAh[0][k], Bl);
                            mma16816(a0, XAl[0][k], Bh);
                            mma16816(a1, XAh[1][k], Bh);
                            mma16816(a1, XAh[1][k], Bl);
                            mma16816(a1, XAl[1][k], Bh);
                        }
                        int hc = c * 64 + n * 8 + c2;
                        float bv0 = sb1[b * 256 + hc];
                        float bv1 = sb1[b * 256 + hc + 1];
                        int odd = nn * 2;
                        HAh[0][odd] = pack_split(fmaxf(a0[0] + bv0, 0.f),
                                                 fmaxf(a0[1] + bv1, 0.f), HAl[0][odd]);
                        HAh[0][odd + 1] = pack_split(fmaxf(a0[2] + bv0, 0.f),
                                                     fmaxf(a0[3] + bv1, 0.f), HAl[0][odd + 1]);
                        HAh[1][odd] = pack_split(fmaxf(a1[0] + bv0, 0.f),
                                                 fmaxf(a1[1] + bv1, 0.f), HAl[1][odd]);
                        HAh[1][odd + 1] = pack_split(fmaxf(a1[2] + bv0, 0.f),
                                                     fmaxf(a1[3] + bv1, 0.f), HAl[1][odd + 1]);
                    }
                    // GEMM2: outAcc += H_kfrag @ W2[c*64 + kk*16 .. +16, :]
                    #pragma unroll
                    for (int n = 0; n < 8; n++) {
                        uint32_t Bh[2], Bl[2];
                        uint32_t ba = sb + (uint32_t)(c * 64 + kk * 16 + l15) * 144
                                         + (uint32_t)(n * 8) * 2;
                        ldsm_x2t(Bh, ba + OFF_W2H);
                        ldsm_x2t(Bl, ba + OFF_W2L);
                        mma16816(outAcc[0][n], HAh[0], Bh);
                        mma16816(outAcc[0][n], HAh[0], Bl);
                        mma16816(outAcc[0][n], HAl[0], Bh);
                        mma16816(outAcc[1][n], HAh[1], Bh);
                        mma16816(outAcc[1][n], HAh[1], Bl);
                        mma16816(outAcc[1][n], HAl[1], Bh);
                    }
                }
            }
        }

        // ---- tile epilogue: out = relu(accS + accN + bs2 + bn2) ----
        #pragma unroll
        for (int rs = 0; rs < 2; rs++) {
            int gr0 = t * 256 + wid * 32 + rs * 16 + r_in;
            int gr1 = gr0 + 8;
            if (gr0 < TT) {
                float* po = out + (size_t)gr0 * 64 + c2;
                #pragma unroll
                for (int n = 0; n < 8; n++)
                    *(float2*)(po + n * 8) = make_float2(
                        fmaxf(outAcc[rs][n][0] + sb2c[n * 8 + c2], 0.f),
                        fmaxf(outAcc[rs][n][1] + sb2c[n * 8 + c2 + 1], 0.f));
            }
            if (gr1 < TT) {
                float* po = out + (size_t)gr1 * 64 + c2;
                #pragma unroll
                for (int n = 0; n < 8; n++)
                    *(float2*)(po + n * 8) = make_float2(
                        fmaxf(outAcc[rs][n][2] + sb2c[n * 8 + c2], 0.f),
                        fmaxf(outAcc[rs][n][3] + sb2c[n * 8 + c2 + 1], 0.f));
            }
        }
    }
}

// ================= launch =================
extern "C" void kernel_launch(void* const* d_in, const int* in_sizes, int n_in,
                              void* d_out, int out_size) {
    const float* h       = (const float*)d_in[0];
    const float* cell    = (const float*)d_in[1];
    const float* attn    = (const float*)d_in[2];
    const float* Wn1     = (const float*)d_in[3];
    const float* bn1     = (const float*)d_in[4];
    const float* Wn2     = (const float*)d_in[5];
    const float* bn2     = (const float*)d_in[6];
    const float* Ws1     = (const float*)d_in[7];
    const float* bs1     = (const float*)d_in[8];
    const float* Ws2     = (const float*)d_in[9];
    const float* bs2     = (const float*)d_in[10];
    const int*   src     = (const int*)d_in[11];
    const int*   dst     = (const int*)d_in[12];
    const int*   targets = (const int*)d_in[13];
    float* out = (float*)d_out;

    cudaFuncSetAttribute(k_mlp4, cudaFuncAttributeMaxDynamicSharedMemorySize, SMEM_TOTAL);

    k_init<<<(NN + 255) / 256, 256>>>();
    k_mark<<<(TT + 255) / 256, 256>>>(targets);
    k_wsplit<<<256, 256>>>(Ws1, Wn1, Ws2, Wn2);
    k_edge1<<<(EE + 255) / 256, 256>>>(src, dst);
    k_scanA<<<NT256, 256>>>();
    k_scanB<<<1, 512>>>();
    k_scanC<<<NT256, 256>>>();
    k_scatter<<<2048, 256>>>();
    k_gather<<<(MAXSLOT + 7) / 8, 256>>>(h, attn);
    k_mlp4<<<GRID_MLP, 256, SMEM_TOTAL>>>(cell, bn1, bn2, bs1, bs2, targets, out);
}